// round 6
// baseline (speedup 1.0000x reference)
#include <cuda_runtime.h>
#include <math.h>
#include <stdint.h>

// Problem dims
#define TT 256
#define BB 64
#define EE 512
#define HH 1024
#define VV 10000
#define MALL (TT*BB)          // 16384
#define NG (4*HH)             // 4096 packed gate columns
#define HREGION ((size_t)MALL*HH)      // 16777216 floats (all_h)
#define YBASE   ((size_t)2*MALL*HH)    // 33554432 floats (start of all_y)
#define NBLK 128              // persistent blocks (1 per SM, 148 SMs available)

// Scratch (device globals: no allocations allowed)
__device__ float g_Xg[(size_t)MALL * NG];   // 268 MB: x-contribution + bias, packed gate order
__device__ float g_Whp[(size_t)HH * NG];    // 16.8 MB: packed recurrent weights [k][4j+g]
__device__ float g_Wxp[(size_t)EE * NG];    // 8.4 MB: packed input weights
__device__ float g_bgp[NG];
__device__ unsigned g_barc = 0;             // grid barrier count (self-resets to 0)
__device__ unsigned g_barg = 0;             // grid barrier generation (monotonic)

__device__ __forceinline__ unsigned f2tf(float x){
    unsigned u; asm("cvt.rna.tf32.f32 %0, %1;" : "=r"(u) : "f"(x)); return u;
}

__device__ __forceinline__ void mma_tf32(float* c, const unsigned* a, const unsigned* b){
    asm("mma.sync.aligned.m16n8k8.row.col.f32.tf32.tf32.f32 "
        "{%0,%1,%2,%3},{%4,%5,%6,%7},{%8,%9},{%0,%1,%2,%3};"
        : "+f"(c[0]), "+f"(c[1]), "+f"(c[2]), "+f"(c[3])
        : "r"(a[0]), "r"(a[1]), "r"(a[2]), "r"(a[3]), "r"(b[0]), "r"(b[1]));
}

// ---------------------------------------------------------------------------
// Pack gate weights/bias into interleaved layout: col p = 4*j + gate (f,i,c,o)
// ---------------------------------------------------------------------------
__global__ void pack_kernel(const float* __restrict__ Wf, const float* __restrict__ Wi,
                            const float* __restrict__ Wc, const float* __restrict__ Wo,
                            const float* __restrict__ bf, const float* __restrict__ bi,
                            const float* __restrict__ bc, const float* __restrict__ bo){
    int stride = gridDim.x * blockDim.x;
    int idx = blockIdx.x * blockDim.x + threadIdx.x;
    const int total = (EE + HH) * HH;
    for (int i = idx; i < total; i += stride){
        int k = i >> 10;
        int j = i & (HH - 1);
        float vf = Wf[i], vi = Wi[i], vc = Wc[i], vo = Wo[i];
        int p = j << 2;
        if (k < HH){
            float* d = g_Whp + (size_t)k * NG + p;
            d[0] = vf; d[1] = vi; d[2] = vc; d[3] = vo;
        } else {
            float* d = g_Wxp + (size_t)(k - HH) * NG + p;
            d[0] = vf; d[1] = vi; d[2] = vc; d[3] = vo;
        }
    }
    for (int j = idx; j < HH; j += stride){
        g_bgp[4*j+0] = bf[j]; g_bgp[4*j+1] = bi[j];
        g_bgp[4*j+2] = bc[j]; g_bgp[4*j+3] = bo[j];
    }
}

// ---------------------------------------------------------------------------
// GEMM A: g_Xg[m, p] = sum_k emb[x[m], k] * g_Wxp[k, p] + g_bgp[p]
// ---------------------------------------------------------------------------
__global__ __launch_bounds__(256) void gemm_xproj(const int* __restrict__ x,
                                                  const float* __restrict__ emb){
    __shared__ float As[128][36];
    __shared__ float Bs[32][132];
    const int m0 = blockIdx.y << 7;
    const int n0 = blockIdx.x << 7;
    const int tid = threadIdx.x;
    const int w = tid >> 5, lane = tid & 31;
    const int g = lane >> 2, qi = lane & 3;
    const int wm = (w & 1) << 6, wn = (w >> 1) << 5;

    float acc[4][4][4];
#pragma unroll
    for (int a=0;a<4;++a)
#pragma unroll
    for (int b=0;b<4;++b)
#pragma unroll
    for (int c2=0;c2<4;++c2) acc[a][b][c2] = 0.f;

    int arow[4], akv[4];
    const float* aptr[4];
#pragma unroll
    for (int q=0;q<4;++q){
        int fi = tid + (q<<8);
        arow[q] = fi >> 3; akv[q] = fi & 7;
        aptr[q] = emb + (size_t)x[m0 + arow[q]] * EE + (akv[q]<<2);
    }
    int bkk[4], bnv[4];
    const float* bptr[4];
#pragma unroll
    for (int q=0;q<4;++q){
        int fi = tid + (q<<8);
        bkk[q] = fi >> 5; bnv[q] = fi & 31;
        bptr[q] = g_Wxp + (size_t)bkk[q]*NG + n0 + (bnv[q]<<2);
    }
    float4 ar[4], br[4];
#pragma unroll
    for (int q=0;q<4;++q) ar[q] = *(const float4*)aptr[q];
#pragma unroll
    for (int q=0;q<4;++q) br[q] = *(const float4*)bptr[q];

    const int KT = EE/32;
    for (int kt = 0; kt < KT; ++kt){
#pragma unroll
        for (int q=0;q<4;++q){
            uint4 u; u.x=f2tf(ar[q].x); u.y=f2tf(ar[q].y); u.z=f2tf(ar[q].z); u.w=f2tf(ar[q].w);
            *reinterpret_cast<uint4*>(&As[arow[q]][akv[q]<<2]) = u;
        }
#pragma unroll
        for (int q=0;q<4;++q){
            uint4 u; u.x=f2tf(br[q].x); u.y=f2tf(br[q].y); u.z=f2tf(br[q].z); u.w=f2tf(br[q].w);
            *reinterpret_cast<uint4*>(&Bs[bkk[q]][bnv[q]<<2]) = u;
        }
        __syncthreads();
        if (kt+1 < KT){
#pragma unroll
            for (int q=0;q<4;++q) ar[q] = *(const float4*)(aptr[q] + (kt+1)*32);
#pragma unroll
            for (int q=0;q<4;++q) br[q] = *(const float4*)(bptr[q] + (size_t)(kt+1)*32*NG);
        }
#pragma unroll
        for (int ks=0; ks<4; ++ks){
            const int kb = ks<<3;
            unsigned af[4][4];
#pragma unroll
            for (int mf=0; mf<4; ++mf){
                int r = wm + (mf<<4) + g;
                af[mf][0] = __float_as_uint(As[r  ][kb+qi]);
                af[mf][1] = __float_as_uint(As[r+8][kb+qi]);
                af[mf][2] = __float_as_uint(As[r  ][kb+qi+4]);
                af[mf][3] = __float_as_uint(As[r+8][kb+qi+4]);
            }
            unsigned bfr[4][2];
#pragma unroll
            for (int nf=0; nf<4; ++nf){
                int cc = wn + (nf<<3) + g;
                bfr[nf][0] = __float_as_uint(Bs[kb+qi  ][cc]);
                bfr[nf][1] = __float_as_uint(Bs[kb+qi+4][cc]);
            }
#pragma unroll
            for (int mf=0; mf<4; ++mf)
#pragma unroll
            for (int nf=0; nf<4; ++nf)
                mma_tf32(acc[mf][nf], af[mf], bfr[nf]);
        }
        __syncthreads();
    }
#pragma unroll
    for (int mf=0; mf<4; ++mf){
        int r0 = m0 + wm + (mf<<4) + g;
#pragma unroll
        for (int nf=0; nf<4; ++nf){
            int col = n0 + wn + (nf<<3) + (qi<<1);
            float b0 = g_bgp[col], b1 = g_bgp[col+1];
            float* d0 = g_Xg + (size_t)r0*NG + col;
            float* d1 = g_Xg + (size_t)(r0+8)*NG + col;
            d0[0] = acc[mf][nf][0] + b0;
            d0[1] = acc[mf][nf][1] + b1;
            d1[0] = acc[mf][nf][2] + b0;
            d1[1] = acc[mf][nf][3] + b1;
        }
    }
}

// ---------------------------------------------------------------------------
// Persistent LSTM recurrence. One kernel runs ALL 256 timesteps.
// 128 blocks (1/SM), block owns 32 packed cols (8 hidden units).
// W slice (1024x32) lives in SMEM for the whole kernel -> zero weight refetch.
// Device-wide sense-reversing spin barrier between steps (self-resetting).
// Block: 256 threads = 8 warps; warp w: row-frag rf=w&3 (16 rows), col-half
// ch=w>>2 (16 cols); 2 n-fragments per warp.
// ---------------------------------------------------------------------------
#define SMEM_STEP_BYTES ((1024*33 + 3*64*36 + 64*33) * 4)   // 171264

__global__ void __launch_bounds__(256) lstm_steps(const float* __restrict__ h0,
                                                  const float* __restrict__ c0,
                                                  float* __restrict__ out){
    extern __shared__ float sm[];
    float* Ws  = sm;                    // [1024][33]  padded, tf32 bits
    float* Hs0 = Ws  + 1024*33;         // [64][36]
    float* Hs1 = Hs0 + 64*36;           // [64][36]
    float* Xs  = Hs1 + 64*36;           // [64][36]
    float* Gs  = Xs  + 64*36;           // [64][33]

    const int p0 = blockIdx.x << 5;
    const int tid = threadIdx.x;
    const int lane = tid & 31, w = tid >> 5;
    const int g = lane >> 2, qi = lane & 3;
    const int rf = w & 3;          // row fragment (rows rf*16 + ...)
    const int ch = w >> 2;         // col half (cols ch*16 + ...)

    // Load W slice (1024 x 32) into SMEM once, converted to tf32
    for (int i = tid; i < 8192; i += 256){
        int k = i >> 3, kv = (i & 7) << 2;
        float4 v = *(const float4*)(g_Whp + (size_t)k * NG + p0 + kv);
        float* d = Ws + k*33 + kv;
        d[0] = __uint_as_float(f2tf(v.x));
        d[1] = __uint_as_float(f2tf(v.y));
        d[2] = __uint_as_float(f2tf(v.z));
        d[3] = __uint_as_float(f2tf(v.w));
    }
    __syncthreads();

    for (int t = 0; t < TT; ++t){
        const float* hprev = t ? out + (size_t)(t-1)*(BB*HH) : h0;
        const float* cprev = t ? out + HREGION + (size_t)(t-1)*(BB*HH) : c0;
        float* hout = out + (size_t)t*(BB*HH);
        float* cout = out + HREGION + (size_t)t*(BB*HH);
        const int m_base = t * BB;

        // Prefetch this step's Xg slice early (DRAM latency overlaps MMA loop)
        float4 xr[2];
#pragma unroll
        for (int q = 0; q < 2; ++q){
            int fi = tid + (q << 8);
            int row = fi >> 3, kv = (fi & 7) << 2;
            xr[q] = *(const float4*)(g_Xg + (size_t)(m_base + row)*NG + p0 + kv);
        }

        float acc[2][4];
#pragma unroll
        for (int a=0;a<2;++a)
#pragma unroll
        for (int b=0;b<4;++b) acc[a][b] = 0.f;

        // Prefetch first h tile
        float4 ar[2];
#pragma unroll
        for (int q = 0; q < 2; ++q){
            int fi = tid + (q << 8);
            int row = fi >> 3, kv = (fi & 7) << 2;
            ar[q] = *(const float4*)(hprev + (size_t)row*HH + kv);
        }

        for (int kt = 0; kt < 32; ++kt){
            float* Hb = (kt & 1) ? Hs1 : Hs0;
#pragma unroll
            for (int q = 0; q < 2; ++q){
                int fi = tid + (q << 8);
                int row = fi >> 3, kv = (fi & 7) << 2;
                float4 u;
                u.x = __uint_as_float(f2tf(ar[q].x));
                u.y = __uint_as_float(f2tf(ar[q].y));
                u.z = __uint_as_float(f2tf(ar[q].z));
                u.w = __uint_as_float(f2tf(ar[q].w));
                *(float4*)(Hb + row*36 + kv) = u;
            }
            __syncthreads();
            if (kt < 31){
                int koff = (kt + 1) << 5;
#pragma unroll
                for (int q = 0; q < 2; ++q){
                    int fi = tid + (q << 8);
                    int row = fi >> 3, kv = (fi & 7) << 2;
                    ar[q] = *(const float4*)(hprev + (size_t)row*HH + koff + kv);
                }
            }
            const float* Wk = Ws + (kt << 5) * 33;
#pragma unroll
            for (int ks = 0; ks < 4; ++ks){
                const int kb = ks << 3;
                const int r = (rf << 4) + g;
                unsigned af[4];
                af[0] = __float_as_uint(Hb[r*36     + kb + qi]);
                af[1] = __float_as_uint(Hb[(r+8)*36 + kb + qi]);
                af[2] = __float_as_uint(Hb[r*36     + kb + qi + 4]);
                af[3] = __float_as_uint(Hb[(r+8)*36 + kb + qi + 4]);
#pragma unroll
                for (int nf = 0; nf < 2; ++nf){
                    int cc = (ch << 4) + (nf << 3) + g;
                    unsigned bfr[2];
                    bfr[0] = __float_as_uint(Wk[(kb + qi    )*33 + cc]);
                    bfr[1] = __float_as_uint(Wk[(kb + qi + 4)*33 + cc]);
                    mma_tf32(acc[nf], af, bfr);
                }
            }
            // no trailing sync needed: double buffer + one sync/iter is safe
        }

        // Stage Xg into SMEM (loads issued at step start), build G, combine.
        __syncthreads();
#pragma unroll
        for (int q = 0; q < 2; ++q){
            int fi = tid + (q << 8);
            int row = fi >> 3, kv = (fi & 7) << 2;
            *(float4*)(Xs + row*36 + kv) = xr[q];
        }
        __syncthreads();
#pragma unroll
        for (int nf = 0; nf < 2; ++nf){
            int r = (rf << 4) + g;
            int col = (ch << 4) + (nf << 3) + (qi << 1);
            Gs[r*33 + col]         = acc[nf][0] + Xs[r*36 + col];
            Gs[r*33 + col + 1]     = acc[nf][1] + Xs[r*36 + col + 1];
            Gs[(r+8)*33 + col]     = acc[nf][2] + Xs[(r+8)*36 + col];
            Gs[(r+8)*33 + col + 1] = acc[nf][3] + Xs[(r+8)*36 + col + 1];
        }
        __syncthreads();
        const int j0 = p0 >> 2;
#pragma unroll
        for (int q = 0; q < 2; ++q){
            int it = tid + (q << 8);
            int r = it >> 3, jj = it & 7;
            float gf = Gs[r*33 + (jj<<2)];
            float gi = Gs[r*33 + (jj<<2) + 1];
            float gc = Gs[r*33 + (jj<<2) + 2];
            float go = Gs[r*33 + (jj<<2) + 3];
            float f = 1.f/(1.f + expf(-gf));
            float i = 1.f/(1.f + expf(-gi));
            float cand = tanhf(gc);
            float o = 1.f/(1.f + expf(-go));
            int jg = j0 + jj;
            float cp = cprev[(size_t)r*HH + jg];
            float cn = f*cp + i*cand;
            float hn = o*tanhf(cn);
            cout[(size_t)r*HH + jg] = cn;
            hout[(size_t)r*HH + jg] = hn;
        }

        // ---- device-wide barrier (sense-reversing, self-resetting) ----
        __threadfence();           // release this thread's h/c writes
        __syncthreads();
        if (tid == 0){
            unsigned gen = *(volatile unsigned*)&g_barg;
            unsigned old = atomicAdd(&g_barc, 1);
            if (old == NBLK - 1){
                g_barc = 0;
                __threadfence();
                atomicAdd(&g_barg, 1);
            } else {
                while (*(volatile unsigned*)&g_barg == gen) __nanosleep(32);
            }
            __threadfence();       // acquire + invalidate L1 before reading peers' h
        }
        __syncthreads();
    }
}

// ---------------------------------------------------------------------------
// GEMM C: Y[m, v] = sum_k all_h[m, k] * Wout[k, v] + bout[v]
// ---------------------------------------------------------------------------
__global__ __launch_bounds__(256) void gemm_out(const float* __restrict__ Hall,
                                                const float* __restrict__ Wout,
                                                const float* __restrict__ bout,
                                                float* __restrict__ Y){
    __shared__ float As[128][36];
    __shared__ float Bs[32][132];
    const int m0 = blockIdx.y << 7;
    const int n0 = blockIdx.x << 7;
    const int tid = threadIdx.x;
    const int w = tid >> 5, lane = tid & 31;
    const int g = lane >> 2, qi = lane & 3;
    const int wm = (w & 1) << 6, wn = (w >> 1) << 5;

    float acc[4][4][4];
#pragma unroll
    for (int a=0;a<4;++a)
#pragma unroll
    for (int b=0;b<4;++b)
#pragma unroll
    for (int c2=0;c2<4;++c2) acc[a][b][c2] = 0.f;

    int arow[4], akv[4];
    const float* aptr[4];
#pragma unroll
    for (int q=0;q<4;++q){
        int fi = tid + (q<<8);
        arow[q] = fi >> 3; akv[q] = fi & 7;
        aptr[q] = Hall + (size_t)(m0 + arow[q])*HH + (akv[q]<<2);
    }
    int bkk[4], bnv[4];
    const float* bptr[4];
    bool bok[4];
#pragma unroll
    for (int q=0;q<4;++q){
        int fi = tid + (q<<8);
        bkk[q] = fi >> 5; bnv[q] = fi & 31;
        bok[q] = (n0 + (bnv[q]<<2)) < VV;
        bptr[q] = Wout + (size_t)bkk[q]*VV + n0 + (bnv[q]<<2);
    }
    float4 ar[4], br[4];
    const float4 z4 = make_float4(0.f,0.f,0.f,0.f);
#pragma unroll
    for (int q=0;q<4;++q) ar[q] = *(const float4*)aptr[q];
#pragma unroll
    for (int q=0;q<4;++q) br[q] = bok[q] ? *(const float4*)bptr[q] : z4;

    const int KT = HH/32;
    for (int kt = 0; kt < KT; ++kt){
#pragma unroll
        for (int q=0;q<4;++q){
            uint4 u; u.x=f2tf(ar[q].x); u.y=f2tf(ar[q].y); u.z=f2tf(ar[q].z); u.w=f2tf(ar[q].w);
            *reinterpret_cast<uint4*>(&As[arow[q]][akv[q]<<2]) = u;
        }
#pragma unroll
        for (int q=0;q<4;++q){
            uint4 u; u.x=f2tf(br[q].x); u.y=f2tf(br[q].y); u.z=f2tf(br[q].z); u.w=f2tf(br[q].w);
            *reinterpret_cast<uint4*>(&Bs[bkk[q]][bnv[q]<<2]) = u;
        }
        __syncthreads();
        if (kt+1 < KT){
#pragma unroll
            for (int q=0;q<4;++q) ar[q] = *(const float4*)(aptr[q] + (kt+1)*32);
#pragma unroll
            for (int q=0;q<4;++q) br[q] = bok[q] ? *(const float4*)(bptr[q] + (size_t)(kt+1)*32*VV) : z4;
        }
#pragma unroll
        for (int ks=0; ks<4; ++ks){
            const int kb = ks<<3;
            unsigned af[4][4];
#pragma unroll
            for (int mf=0; mf<4; ++mf){
                int r = wm + (mf<<4) + g;
                af[mf][0] = __float_as_uint(As[r  ][kb+qi]);
                af[mf][1] = __float_as_uint(As[r+8][kb+qi]);
                af[mf][2] = __float_as_uint(As[r  ][kb+qi+4]);
                af[mf][3] = __float_as_uint(As[r+8][kb+qi+4]);
            }
            unsigned bfr[4][2];
#pragma unroll
            for (int nf=0; nf<4; ++nf){
                int cc = wn + (nf<<3) + g;
                bfr[nf][0] = __float_as_uint(Bs[kb+qi  ][cc]);
                bfr[nf][1] = __float_as_uint(Bs[kb+qi+4][cc]);
            }
#pragma unroll
            for (int mf=0; mf<4; ++mf)
#pragma unroll
            for (int nf=0; nf<4; ++nf)
                mma_tf32(acc[mf][nf], af[mf], bfr[nf]);
        }
        __syncthreads();
    }
#pragma unroll
    for (int mf=0; mf<4; ++mf){
        int r0 = m0 + wm + (mf<<4) + g;
#pragma unroll
        for (int nf=0; nf<4; ++nf){
            int col = n0 + wn + (nf<<3) + (qi<<1);
            if (col < VV){
                float b0 = bout[col], b1 = bout[col+1];
                float* d0 = Y + (size_t)r0*VV + col;
                float* d1 = Y + (size_t)(r0+8)*VV + col;
                d0[0] = acc[mf][nf][0] + b0;
                d0[1] = acc[mf][nf][1] + b1;
                d1[0] = acc[mf][nf][2] + b0;
                d1[1] = acc[mf][nf][3] + b1;
            }
        }
    }
}

// ---------------------------------------------------------------------------
// Launch: pack -> x-projection GEMM -> ONE persistent recurrence kernel -> out GEMM
// d_out layout (float32): all_h [T,B,H] | all_c [T,B,H] | all_y [T,B,V]
// ---------------------------------------------------------------------------
extern "C" void kernel_launch(void* const* d_in, const int* in_sizes, int n_in,
                              void* d_out, int out_size){
    (void)in_sizes; (void)n_in; (void)out_size;
    const int*   x      = (const int*)  d_in[0];
    const float* h_in   = (const float*)d_in[1];
    const float* c_in   = (const float*)d_in[2];
    const float* emb    = (const float*)d_in[3];
    const float* Wf_w   = (const float*)d_in[4];
    const float* Wf_b   = (const float*)d_in[5];
    const float* Wi_w   = (const float*)d_in[6];
    const float* Wi_b   = (const float*)d_in[7];
    const float* Wc_w   = (const float*)d_in[8];
    const float* Wc_b   = (const float*)d_in[9];
    const float* Wo_w   = (const float*)d_in[10];
    const float* Wo_b   = (const float*)d_in[11];
    const float* Wout_w = (const float*)d_in[12];
    const float* Wout_b = (const float*)d_in[13];
    float* out = (float*)d_out;

    static int attr_done = 0;
    if (!attr_done){
        cudaFuncSetAttribute(lstm_steps, cudaFuncAttributeMaxDynamicSharedMemorySize,
                             SMEM_STEP_BYTES);
        attr_done = 1;
    }

    pack_kernel<<<256, 256>>>(Wf_w, Wi_w, Wc_w, Wo_w, Wf_b, Wi_b, Wc_b, Wo_b);

    gemm_xproj<<<dim3(NG/128, MALL/128), 256>>>(x, emb);

    lstm_steps<<<NBLK, 256, SMEM_STEP_BYTES>>>(h_in, c_in, out);

    gemm_out<<<dim3((VV + 127)/128, MALL/128), 256>>>(out, Wout_w, Wout_b, out + YBASE);
}

// round 10
// speedup vs baseline: 1.7651x; 1.7651x over previous
#include <cuda_runtime.h>
#include <math.h>
#include <stdint.h>

// Problem dims
#define TT 256
#define BB 64
#define EE 512
#define HH 1024
#define VV 10000
#define MALL (TT*BB)          // 16384
#define NG (4*HH)             // 4096 packed gate columns
#define HREGION ((size_t)MALL*HH)      // 16777216 floats (all_h)
#define YBASE   ((size_t)2*MALL*HH)    // 33554432 floats (start of all_y)
#define NBLK 128              // persistent blocks (1 per SM)

// Scratch (device globals: no allocations allowed)
__device__ float g_Xg[(size_t)MALL * NG];   // x-contribution + bias, packed gate order
__device__ float g_Whp[(size_t)HH * NG];    // packed recurrent weights [k][4j+g]
__device__ float g_Wxp[(size_t)EE * NG];    // packed input weights
__device__ float g_bgp[NG];
__device__ float g_Htf[2][BB*HH];           // tf32-rounded h ping-pong for MMA consumption
__device__ unsigned g_barc = 0;             // grid barrier count (self-resets)
__device__ unsigned g_barg = 0;             // grid barrier generation (monotonic)

__device__ __forceinline__ unsigned f2tf(float x){
    unsigned u; asm("cvt.rna.tf32.f32 %0, %1;" : "=r"(u) : "f"(x)); return u;
}

__device__ __forceinline__ void mma_tf32(float* c, const unsigned* a, const unsigned* b){
    asm("mma.sync.aligned.m16n8k8.row.col.f32.tf32.tf32.f32 "
        "{%0,%1,%2,%3},{%4,%5,%6,%7},{%8,%9},{%0,%1,%2,%3};"
        : "+f"(c[0]), "+f"(c[1]), "+f"(c[2]), "+f"(c[3])
        : "r"(a[0]), "r"(a[1]), "r"(a[2]), "r"(a[3]), "r"(b[0]), "r"(b[1]));
}

__device__ __forceinline__ void cp_async16(uint32_t dst, const void* src){
    asm volatile("cp.async.cg.shared.global [%0], [%1], 16;\n" :: "r"(dst), "l"(src));
}
__device__ __forceinline__ void cp_commit(){
    asm volatile("cp.async.commit_group;\n");
}
template<int N> __device__ __forceinline__ void cp_wait(){
    asm volatile("cp.async.wait_group %0;\n" :: "n"(N));
}

// ---------------------------------------------------------------------------
// Pack gate weights/bias: col p = 4*j + gate (f,i,c,o)
// ---------------------------------------------------------------------------
__global__ void pack_kernel(const float* __restrict__ Wf, const float* __restrict__ Wi,
                            const float* __restrict__ Wc, const float* __restrict__ Wo,
                            const float* __restrict__ bf, const float* __restrict__ bi,
                            const float* __restrict__ bc, const float* __restrict__ bo){
    int stride = gridDim.x * blockDim.x;
    int idx = blockIdx.x * blockDim.x + threadIdx.x;
    const int total = (EE + HH) * HH;
    for (int i = idx; i < total; i += stride){
        int k = i >> 10;
        int j = i & (HH - 1);
        float vf = Wf[i], vi = Wi[i], vc = Wc[i], vo = Wo[i];
        int p = j << 2;
        if (k < HH){
            float* d = g_Whp + (size_t)k * NG + p;
            d[0] = vf; d[1] = vi; d[2] = vc; d[3] = vo;
        } else {
            float* d = g_Wxp + (size_t)(k - HH) * NG + p;
            d[0] = vf; d[1] = vi; d[2] = vc; d[3] = vo;
        }
    }
    for (int j = idx; j < HH; j += stride){
        g_bgp[4*j+0] = bf[j]; g_bgp[4*j+1] = bi[j];
        g_bgp[4*j+2] = bc[j]; g_bgp[4*j+3] = bo[j];
    }
}

// ---------------------------------------------------------------------------
// GEMM A: g_Xg[m, p] = sum_k emb[x[m], k] * g_Wxp[k, p] + g_bgp[p]
// ---------------------------------------------------------------------------
__global__ __launch_bounds__(256) void gemm_xproj(const int* __restrict__ x,
                                                  const float* __restrict__ emb){
    __shared__ float As[128][36];
    __shared__ float Bs[32][132];
    const int m0 = blockIdx.y << 7;
    const int n0 = blockIdx.x << 7;
    const int tid = threadIdx.x;
    const int w = tid >> 5, lane = tid & 31;
    const int g = lane >> 2, qi = lane & 3;
    const int wm = (w & 1) << 6, wn = (w >> 1) << 5;

    float acc[4][4][4];
#pragma unroll
    for (int a=0;a<4;++a)
#pragma unroll
    for (int b=0;b<4;++b)
#pragma unroll
    for (int c2=0;c2<4;++c2) acc[a][b][c2] = 0.f;

    int arow[4], akv[4];
    const float* aptr[4];
#pragma unroll
    for (int q=0;q<4;++q){
        int fi = tid + (q<<8);
        arow[q] = fi >> 3; akv[q] = fi & 7;
        aptr[q] = emb + (size_t)x[m0 + arow[q]] * EE + (akv[q]<<2);
    }
    int bkk[4], bnv[4];
    const float* bptr[4];
#pragma unroll
    for (int q=0;q<4;++q){
        int fi = tid + (q<<8);
        bkk[q] = fi >> 5; bnv[q] = fi & 31;
        bptr[q] = g_Wxp + (size_t)bkk[q]*NG + n0 + (bnv[q]<<2);
    }
    float4 ar[4], br[4];
#pragma unroll
    for (int q=0;q<4;++q) ar[q] = *(const float4*)aptr[q];
#pragma unroll
    for (int q=0;q<4;++q) br[q] = *(const float4*)bptr[q];

    const int KT = EE/32;
    for (int kt = 0; kt < KT; ++kt){
#pragma unroll
        for (int q=0;q<4;++q){
            uint4 u; u.x=f2tf(ar[q].x); u.y=f2tf(ar[q].y); u.z=f2tf(ar[q].z); u.w=f2tf(ar[q].w);
            *reinterpret_cast<uint4*>(&As[arow[q]][akv[q]<<2]) = u;
        }
#pragma unroll
        for (int q=0;q<4;++q){
            uint4 u; u.x=f2tf(br[q].x); u.y=f2tf(br[q].y); u.z=f2tf(br[q].z); u.w=f2tf(br[q].w);
            *reinterpret_cast<uint4*>(&Bs[bkk[q]][bnv[q]<<2]) = u;
        }
        __syncthreads();
        if (kt+1 < KT){
#pragma unroll
            for (int q=0;q<4;++q) ar[q] = *(const float4*)(aptr[q] + (kt+1)*32);
#pragma unroll
            for (int q=0;q<4;++q) br[q] = *(const float4*)(bptr[q] + (size_t)(kt+1)*32*NG);
        }
#pragma unroll
        for (int ks=0; ks<4; ++ks){
            const int kb = ks<<3;
            unsigned af[4][4];
#pragma unroll
            for (int mf=0; mf<4; ++mf){
                int r = wm + (mf<<4) + g;
                af[mf][0] = __float_as_uint(As[r  ][kb+qi]);
                af[mf][1] = __float_as_uint(As[r+8][kb+qi]);
                af[mf][2] = __float_as_uint(As[r  ][kb+qi+4]);
                af[mf][3] = __float_as_uint(As[r+8][kb+qi+4]);
            }
            unsigned bfr[4][2];
#pragma unroll
            for (int nf=0; nf<4; ++nf){
                int cc = wn + (nf<<3) + g;
                bfr[nf][0] = __float_as_uint(Bs[kb+qi  ][cc]);
                bfr[nf][1] = __float_as_uint(Bs[kb+qi+4][cc]);
            }
#pragma unroll
            for (int mf=0; mf<4; ++mf)
#pragma unroll
            for (int nf=0; nf<4; ++nf)
                mma_tf32(acc[mf][nf], af[mf], bfr[nf]);
        }
        __syncthreads();
    }
#pragma unroll
    for (int mf=0; mf<4; ++mf){
        int r0 = m0 + wm + (mf<<4) + g;
#pragma unroll
        for (int nf=0; nf<4; ++nf){
            int col = n0 + wn + (nf<<3) + (qi<<1);
            float b0 = g_bgp[col], b1 = g_bgp[col+1];
            float* d0 = g_Xg + (size_t)r0*NG + col;
            float* d1 = g_Xg + (size_t)(r0+8)*NG + col;
            d0[0] = acc[mf][nf][0] + b0;
            d0[1] = acc[mf][nf][1] + b1;
            d1[0] = acc[mf][nf][2] + b0;
            d1[1] = acc[mf][nf][3] + b1;
        }
    }
}

// ---------------------------------------------------------------------------
// Persistent LSTM recurrence, W-stationary in registers.
// 128 blocks (1/SM), block owns 32 packed cols. 8 warps = 2 col-halves x 4
// K-slabs (256 K each). Warp's W B-frags (16 cols x 256 K = 128 regs) loaded
// ONCE. H streamed per warp-pair in 32-K chunks via cp.async (pre-rounded
// tf32 bits from g_Htf ping-pong). Pair-local named barrier in the hot loop;
// one block sync + SMEM split-K reduction per step; grid barrier per step.
// ---------------------------------------------------------------------------
// SMEM: Hb [4 pairs][2 bufs][64*36] = 18432 f | Ps [4][64*34] = 8704 f | Xs 2304 f
#define SMEM_LSTM ((18432 + 8704 + 2304) * 4)

__device__ __forceinline__ void grid_bar(){
    __threadfence();
    __syncthreads();
    if (threadIdx.x == 0){
        unsigned gen = *(volatile unsigned*)&g_barg;
        unsigned old = atomicAdd(&g_barc, 1);
        if (old == NBLK - 1){
            g_barc = 0;
            __threadfence();
            atomicAdd(&g_barg, 1);
        } else {
            while (*(volatile unsigned*)&g_barg == gen) __nanosleep(32);
        }
        __threadfence();
    }
    __syncthreads();
}

__global__ void __launch_bounds__(256, 1) lstm_steps(const float* __restrict__ h0,
                                                     const float* __restrict__ c0,
                                                     float* __restrict__ out){
    extern __shared__ float sm[];
    float* Ps = sm + 18432;
    float* Xs = Ps + 8704;

    const int tid = threadIdx.x;
    const int lane = tid & 31;
    const int w = tid >> 5;
    const int g = lane >> 2, qi = lane & 3;
    const int ch = w & 1;            // col half (16 cols)
    const int slab = w >> 1;         // K-slab (256 K) == pair id
    const int p0 = blockIdx.x << 5;
    const int kb0 = slab << 8;
    const int j0 = p0 >> 2;

    float* Hb0 = sm + slab * 2 * 2304;
    float* Hb1 = Hb0 + 2304;
    const uint32_t Hb0a = (uint32_t)__cvta_generic_to_shared(Hb0);
    const uint32_t Hb1a = (uint32_t)__cvta_generic_to_shared(Hb1);
    const int barid = slab + 1;

    // ---- W B-fragments into registers (once) ----
    unsigned breg[32][2][2];
#pragma unroll
    for (int s = 0; s < 32; ++s){
        int k = kb0 + (s << 3);
#pragma unroll
        for (int nf = 0; nf < 2; ++nf){
            int col = p0 + (ch << 4) + (nf << 3) + g;
            breg[s][nf][0] = f2tf(g_Whp[(size_t)(k + qi    ) * NG + col]);
            breg[s][nf][1] = f2tf(g_Whp[(size_t)(k + qi + 4) * NG + col]);
        }
    }

    // ---- h0 -> tf32 copy (block's share), then sync all blocks ----
    {
        int i0 = blockIdx.x << 9;            // 512 per block, 128*512 = 65536
#pragma unroll
        for (int q = 0; q < 2; ++q){
            int i = i0 + tid + (q << 8);
            g_Htf[0][i] = __uint_as_float(f2tf(h0[i]));
        }
    }
    grid_bar();

    for (int t = 0; t < TT; ++t){
        const float* htf   = g_Htf[t & 1];
        float*       htf_n = g_Htf[(t + 1) & 1];
        const float* cprev = t ? out + HREGION + (size_t)(t-1)*(BB*HH) : c0;
        float* hout = out + (size_t)t*(BB*HH);
        float* cout = out + HREGION + (size_t)t*(BB*HH);
        const int m_base = t * BB;

        // prefetch Xg slice + cprev values (consumed in epilogue)
        float4 xr[2];
#pragma unroll
        for (int q = 0; q < 2; ++q){
            int fi = tid + (q << 8);
            int row = fi >> 3, kv = (fi & 7) << 2;
            xr[q] = *(const float4*)(g_Xg + (size_t)(m_base + row)*NG + p0 + kv);
        }
        float cpf[2];
#pragma unroll
        for (int q = 0; q < 2; ++q){
            int it = tid + (q << 8);
            int r = it >> 3, jj = it & 7;
            cpf[q] = cprev[(size_t)r*HH + j0 + jj];
        }

        float acc[4][2][4];
#pragma unroll
        for (int a=0;a<4;++a)
#pragma unroll
        for (int b=0;b<2;++b)
#pragma unroll
        for (int c2=0;c2<4;++c2) acc[a][b][c2] = 0.f;

        // issue chunk 0
#pragma unroll
        for (int i = 0; i < 8; ++i){
            int row = (ch << 5) + (lane >> 3) + (i << 2);
            int seg = lane & 7;
            cp_async16(Hb0a + (row*36 + (seg << 2))*4,
                       htf + (size_t)row*HH + kb0 + (seg << 2));
        }
        cp_commit();

#pragma unroll
        for (int c = 0; c < 8; ++c){
            cp_wait<0>();
            asm volatile("bar.sync %0, 64;" :: "r"(barid));
            if (c < 7){
                uint32_t dsta = (c & 1) ? Hb0a : Hb1a;   // buffer (c+1)&1
#pragma unroll
                for (int i = 0; i < 8; ++i){
                    int row = (ch << 5) + (lane >> 3) + (i << 2);
                    int seg = lane & 7;
                    cp_async16(dsta + (row*36 + (seg << 2))*4,
                               htf + (size_t)row*HH + kb0 + ((c+1) << 5) + (seg << 2));
                }
                cp_commit();
            }
            const float* Hbc = (c & 1) ? Hb1 : Hb0;
#pragma unroll
            for (int ks = 0; ks < 4; ++ks){
                const int kb = ks << 3;
                const int s = (c << 2) + ks;
#pragma unroll
                for (int mf = 0; mf < 4; ++mf){
                    const int r = (mf << 4) + g;
                    unsigned af[4];
                    af[0] = __float_as_uint(Hbc[r*36     + kb + qi]);
                    af[1] = __float_as_uint(Hbc[(r+8)*36 + kb + qi]);
                    af[2] = __float_as_uint(Hbc[r*36     + kb + qi + 4]);
                    af[3] = __float_as_uint(Hbc[(r+8)*36 + kb + qi + 4]);
                    mma_tf32(acc[mf][0], af, breg[s][0]);
                    mma_tf32(acc[mf][1], af, breg[s][1]);
                }
            }
        }

        // stage Xg + split-K partials
#pragma unroll
        for (int q = 0; q < 2; ++q){
            int fi = tid + (q << 8);
            int row = fi >> 3, kv = (fi & 7) << 2;
            *(float4*)(Xs + row*36 + kv) = xr[q];
        }
        float* Pw = Ps + slab * (64*34);
#pragma unroll
        for (int mf = 0; mf < 4; ++mf){
            int r = (mf << 4) + g;
#pragma unroll
            for (int nf = 0; nf < 2; ++nf){
                int col = (ch << 4) + (nf << 3) + (qi << 1);
                *(float2*)(Pw + r*34 + col)     = make_float2(acc[mf][nf][0], acc[mf][nf][1]);
                *(float2*)(Pw + (r+8)*34 + col) = make_float2(acc[mf][nf][2], acc[mf][nf][3]);
            }
        }
        __syncthreads();

        // combine: reduce 4 slabs + Xg, activations, write h/c (+ tf32 h copy)
#pragma unroll
        for (int q = 0; q < 2; ++q){
            int it = tid + (q << 8);
            int r = it >> 3, jj = it & 7;
            int cb = jj << 2;
            int pr = r*34 + cb;
            float gf = Xs[r*36 + cb    ] + Ps[pr    ] + Ps[64*34 + pr    ] + Ps[2*64*34 + pr    ] + Ps[3*64*34 + pr    ];
            float gi = Xs[r*36 + cb + 1] + Ps[pr + 1] + Ps[64*34 + pr + 1] + Ps[2*64*34 + pr + 1] + Ps[3*64*34 + pr + 1];
            float gc = Xs[r*36 + cb + 2] + Ps[pr + 2] + Ps[64*34 + pr + 2] + Ps[2*64*34 + pr + 2] + Ps[3*64*34 + pr + 2];
            float go = Xs[r*36 + cb + 3] + Ps[pr + 3] + Ps[64*34 + pr + 3] + Ps[2*64*34 + pr + 3] + Ps[3*64*34 + pr + 3];
            float f = 1.f/(1.f + expf(-gf));
            float i = 1.f/(1.f + expf(-gi));
            float cand = tanhf(gc);
            float o = 1.f/(1.f + expf(-go));
            int jg = j0 + jj;
            float cn = f*cpf[q] + i*cand;
            float hn = o*tanhf(cn);
            cout[(size_t)r*HH + jg] = cn;
            hout[(size_t)r*HH + jg] = hn;
            htf_n[(size_t)r*HH + jg] = __uint_as_float(f2tf(hn));
        }

        grid_bar();
    }
}

// ---------------------------------------------------------------------------
// GEMM C: Y[m, v] = sum_k all_h[m, k] * Wout[k, v] + bout[v]
// ---------------------------------------------------------------------------
__global__ __launch_bounds__(256) void gemm_out(const float* __restrict__ Hall,
                                                const float* __restrict__ Wout,
                                                const float* __restrict__ bout,
                                                float* __restrict__ Y){
    __shared__ float As[128][36];
    __shared__ float Bs[32][132];
    const int m0 = blockIdx.y << 7;
    const int n0 = blockIdx.x << 7;
    const int tid = threadIdx.x;
    const int w = tid >> 5, lane = tid & 31;
    const int g = lane >> 2, qi = lane & 3;
    const int wm = (w & 1) << 6, wn = (w >> 1) << 5;

    float acc[4][4][4];
#pragma unroll
    for (int a=0;a<4;++a)
#pragma unroll
    for (int b=0;b<4;++b)
#pragma unroll
    for (int c2=0;c2<4;++c2) acc[a][b][c2] = 0.f;

    int arow[4], akv[4];
    const float* aptr[4];
#pragma unroll
    for (int q=0;q<4;++q){
        int fi = tid + (q<<8);
        arow[q] = fi >> 3; akv[q] = fi & 7;
        aptr[q] = Hall + (size_t)(m0 + arow[q])*HH + (akv[q]<<2);
    }
    int bkk[4], bnv[4];
    const float* bptr[4];
    bool bok[4];
#pragma unroll
    for (int q=0;q<4;++q){
        int fi = tid + (q<<8);
        bkk[q] = fi >> 5; bnv[q] = fi & 31;
        bok[q] = (n0 + (bnv[q]<<2)) < VV;
        bptr[q] = Wout + (size_t)bkk[q]*VV + n0 + (bnv[q]<<2);
    }
    float4 ar[4], br[4];
    const float4 z4 = make_float4(0.f,0.f,0.f,0.f);
#pragma unroll
    for (int q=0;q<4;++q) ar[q] = *(const float4*)aptr[q];
#pragma unroll
    for (int q=0;q<4;++q) br[q] = bok[q] ? *(const float4*)bptr[q] : z4;

    const int KT = HH/32;
    for (int kt = 0; kt < KT; ++kt){
#pragma unroll
        for (int q=0;q<4;++q){
            uint4 u; u.x=f2tf(ar[q].x); u.y=f2tf(ar[q].y); u.z=f2tf(ar[q].z); u.w=f2tf(ar[q].w);
            *reinterpret_cast<uint4*>(&As[arow[q]][akv[q]<<2]) = u;
        }
#pragma unroll
        for (int q=0;q<4;++q){
            uint4 u; u.x=f2tf(br[q].x); u.y=f2tf(br[q].y); u.z=f2tf(br[q].z); u.w=f2tf(br[q].w);
            *reinterpret_cast<uint4*>(&Bs[bkk[q]][bnv[q]<<2]) = u;
        }
        __syncthreads();
        if (kt+1 < KT){
#pragma unroll
            for (int q=0;q<4;++q) ar[q] = *(const float4*)(aptr[q] + (kt+1)*32);
#pragma unroll
            for (int q=0;q<4;++q) br[q] = bok[q] ? *(const float4*)(bptr[q] + (size_t)(kt+1)*32*VV) : z4;
        }
#pragma unroll
        for (int ks=0; ks<4; ++ks){
            const int kb = ks<<3;
            unsigned af[4][4];
#pragma unroll
            for (int mf=0; mf<4; ++mf){
                int r = wm + (mf<<4) + g;
                af[mf][0] = __float_as_uint(As[r  ][kb+qi]);
                af[mf][1] = __float_as_uint(As[r+8][kb+qi]);
                af[mf][2] = __float_as_uint(As[r  ][kb+qi+4]);
                af[mf][3] = __float_as_uint(As[r+8][kb+qi+4]);
            }
            unsigned bfr[4][2];
#pragma unroll
            for (int nf=0; nf<4; ++nf){
                int cc = wn + (nf<<3) + g;
                bfr[nf][0] = __float_as_uint(Bs[kb+qi  ][cc]);
                bfr[nf][1] = __float_as_uint(Bs[kb+qi+4][cc]);
            }
#pragma unroll
            for (int mf=0; mf<4; ++mf)
#pragma unroll
            for (int nf=0; nf<4; ++nf)
                mma_tf32(acc[mf][nf], af[mf], bfr[nf]);
        }
        __syncthreads();
    }
#pragma unroll
    for (int mf=0; mf<4; ++mf){
        int r0 = m0 + wm + (mf<<4) + g;
#pragma unroll
        for (int nf=0; nf<4; ++nf){
            int col = n0 + wn + (nf<<3) + (qi<<1);
            if (col < VV){
                float b0 = bout[col], b1 = bout[col+1];
                float* d0 = Y + (size_t)r0*VV + col;
                float* d1 = Y + (size_t)(r0+8)*VV + col;
                d0[0] = acc[mf][nf][0] + b0;
                d0[1] = acc[mf][nf][1] + b1;
                d1[0] = acc[mf][nf][2] + b0;
                d1[1] = acc[mf][nf][3] + b1;
            }
        }
    }
}

// ---------------------------------------------------------------------------
// Launch: pack -> x-projection GEMM -> persistent recurrence -> output GEMM
// d_out layout (float32): all_h [T,B,H] | all_c [T,B,H] | all_y [T,B,V]
// ---------------------------------------------------------------------------
extern "C" void kernel_launch(void* const* d_in, const int* in_sizes, int n_in,
                              void* d_out, int out_size){
    (void)in_sizes; (void)n_in; (void)out_size;
    const int*   x      = (const int*)  d_in[0];
    const float* h_in   = (const float*)d_in[1];
    const float* c_in   = (const float*)d_in[2];
    const float* emb    = (const float*)d_in[3];
    const float* Wf_w   = (const float*)d_in[4];
    const float* Wf_b   = (const float*)d_in[5];
    const float* Wi_w   = (const float*)d_in[6];
    const float* Wi_b   = (const float*)d_in[7];
    const float* Wc_w   = (const float*)d_in[8];
    const float* Wc_b   = (const float*)d_in[9];
    const float* Wo_w   = (const float*)d_in[10];
    const float* Wo_b   = (const float*)d_in[11];
    const float* Wout_w = (const float*)d_in[12];
    const float* Wout_b = (const float*)d_in[13];
    float* out = (float*)d_out;

    static int attr_done = 0;
    if (!attr_done){
        cudaFuncSetAttribute(lstm_steps, cudaFuncAttributeMaxDynamicSharedMemorySize,
                             SMEM_LSTM);
        attr_done = 1;
    }

    pack_kernel<<<256, 256>>>(Wf_w, Wi_w, Wc_w, Wo_w, Wf_b, Wi_b, Wc_b, Wo_b);

    gemm_xproj<<<dim3(NG/128, MALL/128), 256>>>(x, emb);

    lstm_steps<<<NBLK, 256, SMEM_LSTM>>>(h_in, c_in, out);

    gemm_out<<<dim3((VV + 127)/128, MALL/128), 256>>>(out, Wout_w, Wout_b, out + YBASE);
}

// round 13
// speedup vs baseline: 2.0935x; 1.1860x over previous
#include <cuda_runtime.h>
#include <math.h>
#include <stdint.h>

// Problem dims
#define TT 256
#define BB 64
#define EE 512
#define HH 1024
#define VV 10000
#define VP 10240              // padded V for tf32 Wout buffer
#define MALL (TT*BB)          // 16384
#define NG (4*HH)             // 4096 packed gate columns
#define HREGION ((size_t)MALL*HH)      // all_h floats
#define YBASE   ((size_t)2*MALL*HH)    // start of all_y
#define NBLK 128              // persistent blocks (1 per SM)

// Scratch (device globals: no allocations allowed)
__device__ float g_Xg[(size_t)MALL * NG];     // x-contribution + bias, packed gate order
__device__ float g_Whp[(size_t)HH * NG];      // packed recurrent weights [k][4j+g]
__device__ float g_Wxp[(size_t)EE * NG];      // packed input weights
__device__ float g_bgp[NG];
__device__ float g_Htfa[(size_t)(TT+1) * BB * HH]; // tf32-rounded h history: slot t+1 = h_t
__device__ float g_Wotf[(size_t)HH * VP];     // tf32-rounded Wout, zero-padded to VP cols
__device__ unsigned g_barc = 0;               // grid barrier count (self-resets)
__device__ unsigned g_barg = 0;               // grid barrier generation (monotonic)

__device__ __forceinline__ unsigned f2tf(float x){
    unsigned u; asm("cvt.rna.tf32.f32 %0, %1;" : "=r"(u) : "f"(x)); return u;
}

__device__ __forceinline__ void mma_tf32(float* c, const unsigned* a, const unsigned* b){
    asm("mma.sync.aligned.m16n8k8.row.col.f32.tf32.tf32.f32 "
        "{%0,%1,%2,%3},{%4,%5,%6,%7},{%8,%9},{%0,%1,%2,%3};"
        : "+f"(c[0]), "+f"(c[1]), "+f"(c[2]), "+f"(c[3])
        : "r"(a[0]), "r"(a[1]), "r"(a[2]), "r"(a[3]), "r"(b[0]), "r"(b[1]));
}

__device__ __forceinline__ void cp_async16(uint32_t dst, const void* src){
    asm volatile("cp.async.cg.shared.global [%0], [%1], 16;\n" :: "r"(dst), "l"(src));
}
__device__ __forceinline__ void cp_commit(){
    asm volatile("cp.async.commit_group;\n");
}
template<int N> __device__ __forceinline__ void cp_wait(){
    asm volatile("cp.async.wait_group %0;\n" :: "n"(N));
}

// ---------------------------------------------------------------------------
// Pack gate weights/bias: col p = 4*j + gate (f,i,c,o)
// ---------------------------------------------------------------------------
__global__ void pack_kernel(const float* __restrict__ Wf, const float* __restrict__ Wi,
                            const float* __restrict__ Wc, const float* __restrict__ Wo,
                            const float* __restrict__ bf, const float* __restrict__ bi,
                            const float* __restrict__ bc, const float* __restrict__ bo){
    int stride = gridDim.x * blockDim.x;
    int idx = blockIdx.x * blockDim.x + threadIdx.x;
    const int total = (EE + HH) * HH;
    for (int i = idx; i < total; i += stride){
        int k = i >> 10;
        int j = i & (HH - 1);
        float vf = Wf[i], vi = Wi[i], vc = Wc[i], vo = Wo[i];
        int p = j << 2;
        if (k < HH){
            float* d = g_Whp + (size_t)k * NG + p;
            d[0] = vf; d[1] = vi; d[2] = vc; d[3] = vo;
        } else {
            float* d = g_Wxp + (size_t)(k - HH) * NG + p;
            d[0] = vf; d[1] = vi; d[2] = vc; d[3] = vo;
        }
    }
    for (int j = idx; j < HH; j += stride){
        g_bgp[4*j+0] = bf[j]; g_bgp[4*j+1] = bi[j];
        g_bgp[4*j+2] = bc[j]; g_bgp[4*j+3] = bo[j];
    }
}

// ---------------------------------------------------------------------------
// Round Wout to tf32 bits, zero-pad cols to VP
// ---------------------------------------------------------------------------
__global__ void round_wout(const float* __restrict__ Wout){
    size_t stride = (size_t)gridDim.x * blockDim.x;
    for (size_t i = (size_t)blockIdx.x * blockDim.x + threadIdx.x;
         i < (size_t)HH * VP; i += stride){
        int k = (int)(i / VP);
        int v = (int)(i % VP);
        g_Wotf[i] = (v < VV) ? __uint_as_float(f2tf(Wout[(size_t)k * VV + v])) : 0.f;
    }
}

// ---------------------------------------------------------------------------
// GEMM A: g_Xg[m, p] = sum_k emb[x[m], k] * g_Wxp[k, p] + g_bgp[p]
// ---------------------------------------------------------------------------
__global__ __launch_bounds__(256) void gemm_xproj(const int* __restrict__ x,
                                                  const float* __restrict__ emb){
    __shared__ float As[128][36];
    __shared__ float Bs[32][132];
    const int m0 = blockIdx.y << 7;
    const int n0 = blockIdx.x << 7;
    const int tid = threadIdx.x;
    const int w = tid >> 5, lane = tid & 31;
    const int g = lane >> 2, qi = lane & 3;
    const int wm = (w & 1) << 6, wn = (w >> 1) << 5;

    float acc[4][4][4];
#pragma unroll
    for (int a=0;a<4;++a)
#pragma unroll
    for (int b=0;b<4;++b)
#pragma unroll
    for (int c2=0;c2<4;++c2) acc[a][b][c2] = 0.f;

    int arow[4], akv[4];
    const float* aptr[4];
#pragma unroll
    for (int q=0;q<4;++q){
        int fi = tid + (q<<8);
        arow[q] = fi >> 3; akv[q] = fi & 7;
        aptr[q] = emb + (size_t)x[m0 + arow[q]] * EE + (akv[q]<<2);
    }
    int bkk[4], bnv[4];
    const float* bptr[4];
#pragma unroll
    for (int q=0;q<4;++q){
        int fi = tid + (q<<8);
        bkk[q] = fi >> 5; bnv[q] = fi & 31;
        bptr[q] = g_Wxp + (size_t)bkk[q]*NG + n0 + (bnv[q]<<2);
    }
    float4 ar[4], br[4];
#pragma unroll
    for (int q=0;q<4;++q) ar[q] = *(const float4*)aptr[q];
#pragma unroll
    for (int q=0;q<4;++q) br[q] = *(const float4*)bptr[q];

    const int KT = EE/32;
    for (int kt = 0; kt < KT; ++kt){
#pragma unroll
        for (int q=0;q<4;++q){
            uint4 u; u.x=f2tf(ar[q].x); u.y=f2tf(ar[q].y); u.z=f2tf(ar[q].z); u.w=f2tf(ar[q].w);
            *reinterpret_cast<uint4*>(&As[arow[q]][akv[q]<<2]) = u;
        }
#pragma unroll
        for (int q=0;q<4;++q){
            uint4 u; u.x=f2tf(br[q].x); u.y=f2tf(br[q].y); u.z=f2tf(br[q].z); u.w=f2tf(br[q].w);
            *reinterpret_cast<uint4*>(&Bs[bkk[q]][bnv[q]<<2]) = u;
        }
        __syncthreads();
        if (kt+1 < KT){
#pragma unroll
            for (int q=0;q<4;++q) ar[q] = *(const float4*)(aptr[q] + (kt+1)*32);
#pragma unroll
            for (int q=0;q<4;++q) br[q] = *(const float4*)(bptr[q] + (size_t)(kt+1)*32*NG);
        }
#pragma unroll
        for (int ks=0; ks<4; ++ks){
            const int kb = ks<<3;
            unsigned af[4][4];
#pragma unroll
            for (int mf=0; mf<4; ++mf){
                int r = wm + (mf<<4) + g;
                af[mf][0] = __float_as_uint(As[r  ][kb+qi]);
                af[mf][1] = __float_as_uint(As[r+8][kb+qi]);
                af[mf][2] = __float_as_uint(As[r  ][kb+qi+4]);
                af[mf][3] = __float_as_uint(As[r+8][kb+qi+4]);
            }
            unsigned bfr[4][2];
#pragma unroll
            for (int nf=0; nf<4; ++nf){
                int cc = wn + (nf<<3) + g;
                bfr[nf][0] = __float_as_uint(Bs[kb+qi  ][cc]);
                bfr[nf][1] = __float_as_uint(Bs[kb+qi+4][cc]);
            }
#pragma unroll
            for (int mf=0; mf<4; ++mf)
#pragma unroll
            for (int nf=0; nf<4; ++nf)
                mma_tf32(acc[mf][nf], af[mf], bfr[nf]);
        }
        __syncthreads();
    }
#pragma unroll
    for (int mf=0; mf<4; ++mf){
        int r0 = m0 + wm + (mf<<4) + g;
#pragma unroll
        for (int nf=0; nf<4; ++nf){
            int col = n0 + wn + (nf<<3) + (qi<<1);
            float b0 = g_bgp[col], b1 = g_bgp[col+1];
            float* d0 = g_Xg + (size_t)r0*NG + col;
            float* d1 = g_Xg + (size_t)(r0+8)*NG + col;
            d0[0] = acc[mf][nf][0] + b0;
            d0[1] = acc[mf][nf][1] + b1;
            d1[0] = acc[mf][nf][2] + b0;
            d1[1] = acc[mf][nf][3] + b1;
        }
    }
}

// ---------------------------------------------------------------------------
// Persistent LSTM recurrence, W-stationary in registers (unchanged structure;
// tf32 h written to full history buffer g_Htfa for the output GEMM).
// ---------------------------------------------------------------------------
#define SMEM_LSTM ((18432 + 8704 + 2304) * 4)

__device__ __forceinline__ void grid_bar(){
    __threadfence();
    __syncthreads();
    if (threadIdx.x == 0){
        unsigned gen = *(volatile unsigned*)&g_barg;
        unsigned old = atomicAdd(&g_barc, 1);
        if (old == NBLK - 1){
            g_barc = 0;
            __threadfence();
            atomicAdd(&g_barg, 1);
        } else {
            while (*(volatile unsigned*)&g_barg == gen) __nanosleep(32);
        }
        __threadfence();
    }
    __syncthreads();
}

__global__ void __launch_bounds__(256, 1) lstm_steps(const float* __restrict__ h0,
                                                     const float* __restrict__ c0,
                                                     float* __restrict__ out){
    extern __shared__ float sm[];
    float* Ps = sm + 18432;
    float* Xs = Ps + 8704;

    const int tid = threadIdx.x;
    const int lane = tid & 31;
    const int w = tid >> 5;
    const int g = lane >> 2, qi = lane & 3;
    const int ch = w & 1;            // col half (16 cols)
    const int slab = w >> 1;         // K-slab (256 K) == pair id
    const int p0 = blockIdx.x << 5;
    const int kb0 = slab << 8;
    const int j0 = p0 >> 2;

    float* Hb0 = sm + slab * 2 * 2304;
    float* Hb1 = Hb0 + 2304;
    const uint32_t Hb0a = (uint32_t)__cvta_generic_to_shared(Hb0);
    const uint32_t Hb1a = (uint32_t)__cvta_generic_to_shared(Hb1);
    const int barid = slab + 1;

    // ---- W B-fragments into registers (once) ----
    unsigned breg[32][2][2];
#pragma unroll
    for (int s = 0; s < 32; ++s){
        int k = kb0 + (s << 3);
#pragma unroll
        for (int nf = 0; nf < 2; ++nf){
            int col = p0 + (ch << 4) + (nf << 3) + g;
            breg[s][nf][0] = f2tf(g_Whp[(size_t)(k + qi    ) * NG + col]);
            breg[s][nf][1] = f2tf(g_Whp[(size_t)(k + qi + 4) * NG + col]);
        }
    }

    // ---- h0 -> tf32 copy into history slot 0 ----
    {
        int i0 = blockIdx.x << 9;
#pragma unroll
        for (int q = 0; q < 2; ++q){
            int i = i0 + tid + (q << 8);
            g_Htfa[i] = __uint_as_float(f2tf(h0[i]));
        }
    }
    grid_bar();

    for (int t = 0; t < TT; ++t){
        const float* htf   = g_Htfa + (size_t)t * (BB*HH);
        float*       htf_n = g_Htfa + (size_t)(t+1) * (BB*HH);
        const float* cprev = t ? out + HREGION + (size_t)(t-1)*(BB*HH) : c0;
        float* hout = out + (size_t)t*(BB*HH);
        float* cout = out + HREGION + (size_t)t*(BB*HH);
        const int m_base = t * BB;

        float4 xr[2];
#pragma unroll
        for (int q = 0; q < 2; ++q){
            int fi = tid + (q << 8);
            int row = fi >> 3, kv = (fi & 7) << 2;
            xr[q] = *(const float4*)(g_Xg + (size_t)(m_base + row)*NG + p0 + kv);
        }
        float cpf[2];
#pragma unroll
        for (int q = 0; q < 2; ++q){
            int it = tid + (q << 8);
            int r = it >> 3, jj = it & 7;
            cpf[q] = cprev[(size_t)r*HH + j0 + jj];
        }

        float acc[4][2][4];
#pragma unroll
        for (int a=0;a<4;++a)
#pragma unroll
        for (int b=0;b<2;++b)
#pragma unroll
        for (int c2=0;c2<4;++c2) acc[a][b][c2] = 0.f;

#pragma unroll
        for (int i = 0; i < 8; ++i){
            int row = (ch << 5) + (lane >> 3) + (i << 2);
            int seg = lane & 7;
            cp_async16(Hb0a + (row*36 + (seg << 2))*4,
                       htf + (size_t)row*HH + kb0 + (seg << 2));
        }
        cp_commit();

#pragma unroll
        for (int c = 0; c < 8; ++c){
            cp_wait<0>();
            asm volatile("bar.sync %0, 64;" :: "r"(barid));
            if (c < 7){
                uint32_t dsta = (c & 1) ? Hb0a : Hb1a;
#pragma unroll
                for (int i = 0; i < 8; ++i){
                    int row = (ch << 5) + (lane >> 3) + (i << 2);
                    int seg = lane & 7;
                    cp_async16(dsta + (row*36 + (seg << 2))*4,
                               htf + (size_t)row*HH + kb0 + ((c+1) << 5) + (seg << 2));
                }
                cp_commit();
            }
            const float* Hbc = (c & 1) ? Hb1 : Hb0;
#pragma unroll
            for (int ks = 0; ks < 4; ++ks){
                const int kb = ks << 3;
                const int s = (c << 2) + ks;
#pragma unroll
                for (int mf = 0; mf < 4; ++mf){
                    const int r = (mf << 4) + g;
                    unsigned af[4];
                    af[0] = __float_as_uint(Hbc[r*36     + kb + qi]);
                    af[1] = __float_as_uint(Hbc[(r+8)*36 + kb + qi]);
                    af[2] = __float_as_uint(Hbc[r*36     + kb + qi + 4]);
                    af[3] = __float_as_uint(Hbc[(r+8)*36 + kb + qi + 4]);
                    mma_tf32(acc[mf][0], af, breg[s][0]);
                    mma_tf32(acc[mf][1], af, breg[s][1]);
                }
            }
        }

#pragma unroll
        for (int q = 0; q < 2; ++q){
            int fi = tid + (q << 8);
            int row = fi >> 3, kv = (fi & 7) << 2;
            *(float4*)(Xs + row*36 + kv) = xr[q];
        }
        float* Pw = Ps + slab * (64*34);
#pragma unroll
        for (int mf = 0; mf < 4; ++mf){
            int r = (mf << 4) + g;
#pragma unroll
            for (int nf = 0; nf < 2; ++nf){
                int col = (ch << 4) + (nf << 3) + (qi << 1);
                *(float2*)(Pw + r*34 + col)     = make_float2(acc[mf][nf][0], acc[mf][nf][1]);
                *(float2*)(Pw + (r+8)*34 + col) = make_float2(acc[mf][nf][2], acc[mf][nf][3]);
            }
        }
        __syncthreads();

#pragma unroll
        for (int q = 0; q < 2; ++q){
            int it = tid + (q << 8);
            int r = it >> 3, jj = it & 7;
            int cb = jj << 2;
            int pr = r*34 + cb;
            float gf = Xs[r*36 + cb    ] + Ps[pr    ] + Ps[64*34 + pr    ] + Ps[2*64*34 + pr    ] + Ps[3*64*34 + pr    ];
            float gi = Xs[r*36 + cb + 1] + Ps[pr + 1] + Ps[64*34 + pr + 1] + Ps[2*64*34 + pr + 1] + Ps[3*64*34 + pr + 1];
            float gc = Xs[r*36 + cb + 2] + Ps[pr + 2] + Ps[64*34 + pr + 2] + Ps[2*64*34 + pr + 2] + Ps[3*64*34 + pr + 2];
            float go = Xs[r*36 + cb + 3] + Ps[pr + 3] + Ps[64*34 + pr + 3] + Ps[2*64*34 + pr + 3] + Ps[3*64*34 + pr + 3];
            float f = 1.f/(1.f + expf(-gf));
            float i = 1.f/(1.f + expf(-gi));
            float cand = tanhf(gc);
            float o = 1.f/(1.f + expf(-go));
            int jg = j0 + jj;
            float cn = f*cpf[q] + i*cand;
            float hn = o*tanhf(cn);
            cout[(size_t)r*HH + jg] = cn;
            hout[(size_t)r*HH + jg] = hn;
            htf_n[(size_t)r*HH + jg] = __uint_as_float(f2tf(hn));
        }

        grid_bar();
    }
}

// ---------------------------------------------------------------------------
// GEMM C: Y[m, v] = sum_k Htfa[slot 1 + ...][k] * Wotf[k, v] + bout[v]
// Block tile 128x256, warp tile 64x64 (8 warps = 2x4). Operands pre-rounded
// tf32 in global; cp.async double-buffered; A base computed IN DEVICE CODE
// (host-side __device__ symbol arithmetic silently reads the host shadow via
// ATS on GB300 -> zeros; that was the R11 bug).
// ---------------------------------------------------------------------------
#define GO_SMEM ((2*128*36 + 2*32*264) * 4)   // 104448 bytes

__global__ __launch_bounds__(256, 1) void gemm_out2(const float* __restrict__ bout,
                                                    float* __restrict__ Y){
    extern __shared__ float smx[];
    float* As0 = smx;
    float* As1 = As0 + 128*36;
    float* Bs0 = As1 + 128*36;
    float* Bs1 = Bs0 + 32*264;
    const uint32_t As0a = (uint32_t)__cvta_generic_to_shared(As0);
    const uint32_t As1a = (uint32_t)__cvta_generic_to_shared(As1);
    const uint32_t Bs0a = (uint32_t)__cvta_generic_to_shared(Bs0);
    const uint32_t Bs1a = (uint32_t)__cvta_generic_to_shared(Bs1);

    const float* Atf = g_Htfa + (size_t)BB * HH;   // slot 1 = h_0; row m = h_{m/64}[m%64]

    const int m0 = blockIdx.y << 7;
    const int n0 = blockIdx.x << 8;
    const int tid = threadIdx.x;
    const int w = tid >> 5, lane = tid & 31;
    const int g = lane >> 2, qi = lane & 3;
    const int wm = (w & 1) << 6;       // 2 row groups of 64
    const int wn = (w >> 1) << 6;      // 4 col groups of 64

    float acc[4][8][4];
#pragma unroll
    for (int a=0;a<4;++a)
#pragma unroll
    for (int b=0;b<8;++b)
#pragma unroll
    for (int c2=0;c2<4;++c2) acc[a][b][c2] = 0.f;

    // A: 128 rows x 32 k = 1024 float4; 4 per thread
    int a_row[4], a_kv[4];
#pragma unroll
    for (int q=0;q<4;++q){
        int fi = tid + (q<<8);
        a_row[q] = fi >> 3; a_kv[q] = (fi & 7) << 2;
    }
    // B: 32 rows x 256 cols = 2048 float4; 8 per thread
    int b_row[8], b_cv[8];
#pragma unroll
    for (int q=0;q<8;++q){
        int fi = tid + (q<<8);
        b_row[q] = fi >> 6; b_cv[q] = (fi & 63) << 2;
    }

    // prologue: tile 0
#pragma unroll
    for (int q=0;q<4;++q)
        cp_async16(As0a + (a_row[q]*36 + a_kv[q])*4,
                   Atf + (size_t)(m0 + a_row[q])*HH + a_kv[q]);
#pragma unroll
    for (int q=0;q<8;++q)
        cp_async16(Bs0a + (b_row[q]*264 + b_cv[q])*4,
                   g_Wotf + (size_t)b_row[q]*VP + n0 + b_cv[q]);
    cp_commit();

    for (int kt = 0; kt < 32; ++kt){
        if (kt < 31){
            const int ko = (kt + 1) << 5;
            uint32_t Ad = (kt & 1) ? As0a : As1a;
            uint32_t Bd = (kt & 1) ? Bs0a : Bs1a;
#pragma unroll
            for (int q=0;q<4;++q)
                cp_async16(Ad + (a_row[q]*36 + a_kv[q])*4,
                           Atf + (size_t)(m0 + a_row[q])*HH + ko + a_kv[q]);
#pragma unroll
            for (int q=0;q<8;++q)
                cp_async16(Bd + (b_row[q]*264 + b_cv[q])*4,
                           g_Wotf + (size_t)(ko + b_row[q])*VP + n0 + b_cv[q]);
            cp_commit();
            cp_wait<1>();
        } else {
            cp_wait<0>();
        }
        __syncthreads();

        const float* Asc = (kt & 1) ? As1 : As0;
        const float* Bsc = (kt & 1) ? Bs1 : Bs0;
#pragma unroll
        for (int ks = 0; ks < 4; ++ks){
            const int kb = ks << 3;
            unsigned bfr[8][2];
#pragma unroll
            for (int nf = 0; nf < 8; ++nf){
                int cc = wn + (nf << 3) + g;
                bfr[nf][0] = __float_as_uint(Bsc[(kb + qi    )*264 + cc]);
                bfr[nf][1] = __float_as_uint(Bsc[(kb + qi + 4)*264 + cc]);
            }
#pragma unroll
            for (int mf = 0; mf < 4; ++mf){
                int r = wm + (mf << 4) + g;
                unsigned af[4];
                af[0] = __float_as_uint(Asc[r*36       + kb + qi]);
                af[1] = __float_as_uint(Asc[(r+8)*36   + kb + qi]);
                af[2] = __float_as_uint(Asc[r*36       + kb + qi + 4]);
                af[3] = __float_as_uint(Asc[(r+8)*36   + kb + qi + 4]);
#pragma unroll
                for (int nf = 0; nf < 8; ++nf)
                    mma_tf32(acc[mf][nf], af, bfr[nf]);
            }
        }
        __syncthreads();
    }

    // epilogue
#pragma unroll
    for (int mf = 0; mf < 4; ++mf){
        int r0 = m0 + wm + (mf << 4) + g;
#pragma unroll
        for (int nf = 0; nf < 8; ++nf){
            int col = n0 + wn + (nf << 3) + (qi << 1);
            if (col < VV){
                float b0 = bout[col], b1 = bout[col+1];
                *(float2*)(Y + (size_t)r0*VV + col) =
                    make_float2(acc[mf][nf][0] + b0, acc[mf][nf][1] + b1);
                *(float2*)(Y + (size_t)(r0+8)*VV + col) =
                    make_float2(acc[mf][nf][2] + b0, acc[mf][nf][3] + b1);
            }
        }
    }
}

// ---------------------------------------------------------------------------
// Launch: pack + round -> x-projection -> persistent recurrence -> output GEMM
// d_out layout (float32): all_h [T,B,H] | all_c [T,B,H] | all_y [T,B,V]
// ---------------------------------------------------------------------------
extern "C" void kernel_launch(void* const* d_in, const int* in_sizes, int n_in,
                              void* d_out, int out_size){
    (void)in_sizes; (void)n_in; (void)out_size;
    const int*   x      = (const int*)  d_in[0];
    const float* h_in   = (const float*)d_in[1];
    const float* c_in   = (const float*)d_in[2];
    const float* emb    = (const float*)d_in[3];
    const float* Wf_w   = (const float*)d_in[4];
    const float* Wf_b   = (const float*)d_in[5];
    const float* Wi_w   = (const float*)d_in[6];
    const float* Wi_b   = (const float*)d_in[7];
    const float* Wc_w   = (const float*)d_in[8];
    const float* Wc_b   = (const float*)d_in[9];
    const float* Wo_w   = (const float*)d_in[10];
    const float* Wo_b   = (const float*)d_in[11];
    const float* Wout_w = (const float*)d_in[12];
    const float* Wout_b = (const float*)d_in[13];
    float* out = (float*)d_out;

    static int attr_done = 0;
    if (!attr_done){
        cudaFuncSetAttribute(lstm_steps, cudaFuncAttributeMaxDynamicSharedMemorySize,
                             SMEM_LSTM);
        cudaFuncSetAttribute(gemm_out2, cudaFuncAttributeMaxDynamicSharedMemorySize,
                             GO_SMEM);
        attr_done = 1;
    }

    pack_kernel<<<256, 256>>>(Wf_w, Wi_w, Wc_w, Wo_w, Wf_b, Wi_b, Wc_b, Wo_b);
    round_wout<<<512, 256>>>(Wout_w);

    gemm_xproj<<<dim3(NG/128, MALL/128), 256>>>(x, emb);

    lstm_steps<<<NBLK, 256, SMEM_LSTM>>>(h_in, c_in, out);

    gemm_out2<<<dim3(VP/256, MALL/128), 256, GO_SMEM>>>(Wout_b, out + YBASE);
}

// round 17
// speedup vs baseline: 2.1173x; 1.0114x over previous
#include <cuda_runtime.h>
#include <math.h>
#include <stdint.h>

// Problem dims
#define TT 256
#define BB 64
#define EE 512
#define HH 1024
#define VV 10000
#define VP 10240              // padded V for tf32 Wout buffer
#define MALL (TT*BB)          // 16384
#define NG (4*HH)             // 4096 packed gate columns
#define HREGION ((size_t)MALL*HH)      // all_h floats
#define YBASE   ((size_t)2*MALL*HH)    // start of all_y
#define NBLK 128              // persistent blocks (1 per SM)

// Scratch (device globals: no allocations allowed)
__device__ float g_Xg[(size_t)MALL * NG];     // x-contribution + bias, packed gate order
__device__ float g_Whp[(size_t)HH * NG];      // packed recurrent weights [k][4j+g]
__device__ float g_Wxp[(size_t)EE * NG];      // packed input weights
__device__ float g_bgp[NG];
__device__ float g_Htfa[(size_t)(TT+1) * BB * HH]; // tf32-rounded h history: slot t+1 = h_t
__device__ float g_Wotf[(size_t)HH * VP];     // tf32-rounded Wout, zero-padded to VP cols
__device__ unsigned g_barc = 0;               // grid barrier count (self-resets)
__device__ unsigned g_barg = 0;               // grid barrier generation (monotonic)

__device__ __forceinline__ unsigned f2tf(float x){
    unsigned u; asm("cvt.rna.tf32.f32 %0, %1;" : "=r"(u) : "f"(x)); return u;
}

__device__ __forceinline__ void mma_tf32(float* c, const unsigned* a, const unsigned* b){
    asm("mma.sync.aligned.m16n8k8.row.col.f32.tf32.tf32.f32 "
        "{%0,%1,%2,%3},{%4,%5,%6,%7},{%8,%9},{%0,%1,%2,%3};"
        : "+f"(c[0]), "+f"(c[1]), "+f"(c[2]), "+f"(c[3])
        : "r"(a[0]), "r"(a[1]), "r"(a[2]), "r"(a[3]), "r"(b[0]), "r"(b[1]));
}

__device__ __forceinline__ void cp_async16(uint32_t dst, const void* src){
    asm volatile("cp.async.cg.shared.global [%0], [%1], 16;\n" :: "r"(dst), "l"(src));
}
__device__ __forceinline__ void cp_commit(){
    asm volatile("cp.async.commit_group;\n");
}
template<int N> __device__ __forceinline__ void cp_wait(){
    asm volatile("cp.async.wait_group %0;\n" :: "n"(N));
}

// ---------------------------------------------------------------------------
// Pack gate weights/bias: col p = 4*j + gate (f,i,c,o)
// ---------------------------------------------------------------------------
__global__ void pack_kernel(const float* __restrict__ Wf, const float* __restrict__ Wi,
                            const float* __restrict__ Wc, const float* __restrict__ Wo,
                            const float* __restrict__ bf, const float* __restrict__ bi,
                            const float* __restrict__ bc, const float* __restrict__ bo){
    int stride = gridDim.x * blockDim.x;
    int idx = blockIdx.x * blockDim.x + threadIdx.x;
    const int total = (EE + HH) * HH;
    for (int i = idx; i < total; i += stride){
        int k = i >> 10;
        int j = i & (HH - 1);
        float vf = Wf[i], vi = Wi[i], vc = Wc[i], vo = Wo[i];
        int p = j << 2;
        if (k < HH){
            float* d = g_Whp + (size_t)k * NG + p;
            d[0] = vf; d[1] = vi; d[2] = vc; d[3] = vo;
        } else {
            float* d = g_Wxp + (size_t)(k - HH) * NG + p;
            d[0] = vf; d[1] = vi; d[2] = vc; d[3] = vo;
        }
    }
    for (int j = idx; j < HH; j += stride){
        g_bgp[4*j+0] = bf[j]; g_bgp[4*j+1] = bi[j];
        g_bgp[4*j+2] = bc[j]; g_bgp[4*j+3] = bo[j];
    }
}

// ---------------------------------------------------------------------------
// Round Wout to tf32 bits, zero-pad cols to VP
// ---------------------------------------------------------------------------
__global__ void round_wout(const float* __restrict__ Wout){
    size_t stride = (size_t)gridDim.x * blockDim.x;
    for (size_t i = (size_t)blockIdx.x * blockDim.x + threadIdx.x;
         i < (size_t)HH * VP; i += stride){
        int k = (int)(i / VP);
        int v = (int)(i % VP);
        g_Wotf[i] = (v < VV) ? __uint_as_float(f2tf(Wout[(size_t)k * VV + v])) : 0.f;
    }
}

// ---------------------------------------------------------------------------
// GEMM A: g_Xg[m, p] = sum_k emb[x[m], k] * g_Wxp[k, p] + g_bgp[p]
// ---------------------------------------------------------------------------
__global__ __launch_bounds__(256) void gemm_xproj(const int* __restrict__ x,
                                                  const float* __restrict__ emb){
    __shared__ float As[128][36];
    __shared__ float Bs[32][132];
    const int m0 = blockIdx.y << 7;
    const int n0 = blockIdx.x << 7;
    const int tid = threadIdx.x;
    const int w = tid >> 5, lane = tid & 31;
    const int g = lane >> 2, qi = lane & 3;
    const int wm = (w & 1) << 6, wn = (w >> 1) << 5;

    float acc[4][4][4];
#pragma unroll
    for (int a=0;a<4;++a)
#pragma unroll
    for (int b=0;b<4;++b)
#pragma unroll
    for (int c2=0;c2<4;++c2) acc[a][b][c2] = 0.f;

    int arow[4], akv[4];
    const float* aptr[4];
#pragma unroll
    for (int q=0;q<4;++q){
        int fi = tid + (q<<8);
        arow[q] = fi >> 3; akv[q] = fi & 7;
        aptr[q] = emb + (size_t)x[m0 + arow[q]] * EE + (akv[q]<<2);
    }
    int bkk[4], bnv[4];
    const float* bptr[4];
#pragma unroll
    for (int q=0;q<4;++q){
        int fi = tid + (q<<8);
        bkk[q] = fi >> 5; bnv[q] = fi & 31;
        bptr[q] = g_Wxp + (size_t)bkk[q]*NG + n0 + (bnv[q]<<2);
    }
    float4 ar[4], br[4];
#pragma unroll
    for (int q=0;q<4;++q) ar[q] = *(const float4*)aptr[q];
#pragma unroll
    for (int q=0;q<4;++q) br[q] = *(const float4*)bptr[q];

    const int KT = EE/32;
    for (int kt = 0; kt < KT; ++kt){
#pragma unroll
        for (int q=0;q<4;++q){
            uint4 u; u.x=f2tf(ar[q].x); u.y=f2tf(ar[q].y); u.z=f2tf(ar[q].z); u.w=f2tf(ar[q].w);
            *reinterpret_cast<uint4*>(&As[arow[q]][akv[q]<<2]) = u;
        }
#pragma unroll
        for (int q=0;q<4;++q){
            uint4 u; u.x=f2tf(br[q].x); u.y=f2tf(br[q].y); u.z=f2tf(br[q].z); u.w=f2tf(br[q].w);
            *reinterpret_cast<uint4*>(&Bs[bkk[q]][bnv[q]<<2]) = u;
        }
        __syncthreads();
        if (kt+1 < KT){
#pragma unroll
            for (int q=0;q<4;++q) ar[q] = *(const float4*)(aptr[q] + (kt+1)*32);
#pragma unroll
            for (int q=0;q<4;++q) br[q] = *(const float4*)(bptr[q] + (size_t)(kt+1)*32*NG);
        }
#pragma unroll
        for (int ks=0; ks<4; ++ks){
            const int kb = ks<<3;
            unsigned af[4][4];
#pragma unroll
            for (int mf=0; mf<4; ++mf){
                int r = wm + (mf<<4) + g;
                af[mf][0] = __float_as_uint(As[r  ][kb+qi]);
                af[mf][1] = __float_as_uint(As[r+8][kb+qi]);
                af[mf][2] = __float_as_uint(As[r  ][kb+qi+4]);
                af[mf][3] = __float_as_uint(As[r+8][kb+qi+4]);
            }
            unsigned bfr[4][2];
#pragma unroll
            for (int nf=0; nf<4; ++nf){
                int cc = wn + (nf<<3) + g;
                bfr[nf][0] = __float_as_uint(Bs[kb+qi  ][cc]);
                bfr[nf][1] = __float_as_uint(Bs[kb+qi+4][cc]);
            }
#pragma unroll
            for (int mf=0; mf<4; ++mf)
#pragma unroll
            for (int nf=0; nf<4; ++nf)
                mma_tf32(acc[mf][nf], af[mf], bfr[nf]);
        }
        __syncthreads();
    }
#pragma unroll
    for (int mf=0; mf<4; ++mf){
        int r0 = m0 + wm + (mf<<4) + g;
#pragma unroll
        for (int nf=0; nf<4; ++nf){
            int col = n0 + wn + (nf<<3) + (qi<<1);
            float b0 = g_bgp[col], b1 = g_bgp[col+1];
            float* d0 = g_Xg + (size_t)r0*NG + col;
            float* d1 = g_Xg + (size_t)(r0+8)*NG + col;
            d0[0] = acc[mf][nf][0] + b0;
            d0[1] = acc[mf][nf][1] + b1;
            d1[0] = acc[mf][nf][2] + b0;
            d1[1] = acc[mf][nf][3] + b1;
        }
    }
}

// ---------------------------------------------------------------------------
// Persistent LSTM recurrence, W-stationary in registers.
// NEW vs R13: 3-buffer, 2-deep cp.async pipeline per warp-pair. Iter c:
//   cp_wait<1> (chunk c landed, c+1 in flight) -> pair bar -> issue c+2 ->
//   compute c. Buffer (c+2)%3 == (c-1)%3 is safe to overwrite: passing the
//   bar at iter c implies the peer finished computing chunk c-1.
// ---------------------------------------------------------------------------
// SMEM: Hb [4 pairs][3 bufs][64*36]=27648 f | Ps [4][64*34]=8704 f | Xs 2304 f
#define SMEM_LSTM ((27648 + 8704 + 2304) * 4)

__device__ __forceinline__ void grid_bar(){
    __threadfence();
    __syncthreads();
    if (threadIdx.x == 0){
        unsigned gen = *(volatile unsigned*)&g_barg;
        unsigned old = atomicAdd(&g_barc, 1);
        if (old == NBLK - 1){
            g_barc = 0;
            __threadfence();
            atomicAdd(&g_barg, 1);
        } else {
            while (*(volatile unsigned*)&g_barg == gen) __nanosleep(32);
        }
        __threadfence();
    }
    __syncthreads();
}

__global__ void __launch_bounds__(256, 1) lstm_steps(const float* __restrict__ h0,
                                                     const float* __restrict__ c0,
                                                     float* __restrict__ out){
    extern __shared__ float sm[];
    float* Ps = sm + 27648;
    float* Xs = Ps + 8704;

    const int tid = threadIdx.x;
    const int lane = tid & 31;
    const int w = tid >> 5;
    const int g = lane >> 2, qi = lane & 3;
    const int ch = w & 1;            // col half (16 cols); also row-half for loads
    const int slab = w >> 1;         // K-slab (256 K) == pair id
    const int p0 = blockIdx.x << 5;
    const int kb0 = slab << 8;
    const int j0 = p0 >> 2;

    float* Hb = sm + slab * 3 * 2304;           // 3 buffers of 64x36
    const uint32_t Hba = (uint32_t)__cvta_generic_to_shared(Hb);
    const int barid = slab + 1;

    // per-thread load coords (each warp fills its 32-row half of the chunk)
    const int l_row = (ch << 5) + (lane >> 3);  // +4*i
    const int l_seg = (lane & 7) << 2;

    // ---- W B-fragments into registers (once) ----
    unsigned breg[32][2][2];
#pragma unroll
    for (int s = 0; s < 32; ++s){
        int k = kb0 + (s << 3);
#pragma unroll
        for (int nf = 0; nf < 2; ++nf){
            int col = p0 + (ch << 4) + (nf << 3) + g;
            breg[s][nf][0] = f2tf(g_Whp[(size_t)(k + qi    ) * NG + col]);
            breg[s][nf][1] = f2tf(g_Whp[(size_t)(k + qi + 4) * NG + col]);
        }
    }

    // ---- h0 -> tf32 copy into history slot 0 ----
    {
        int i0 = blockIdx.x << 9;
#pragma unroll
        for (int q = 0; q < 2; ++q){
            int i = i0 + tid + (q << 8);
            g_Htfa[i] = __uint_as_float(f2tf(h0[i]));
        }
    }
    grid_bar();

    for (int t = 0; t < TT; ++t){
        const float* htf   = g_Htfa + (size_t)t * (BB*HH);
        float*       htf_n = g_Htfa + (size_t)(t+1) * (BB*HH);
        const float* cprev = t ? out + HREGION + (size_t)(t-1)*(BB*HH) : c0;
        float* hout = out + (size_t)t*(BB*HH);
        float* cout = out + HREGION + (size_t)t*(BB*HH);
        const int m_base = t * BB;

        float4 xr[2];
#pragma unroll
        for (int q = 0; q < 2; ++q){
            int fi = tid + (q << 8);
            int row = fi >> 3, kv = (fi & 7) << 2;
            xr[q] = *(const float4*)(g_Xg + (size_t)(m_base + row)*NG + p0 + kv);
        }
        float cpf[2];
#pragma unroll
        for (int q = 0; q < 2; ++q){
            int it = tid + (q << 8);
            int r = it >> 3, jj = it & 7;
            cpf[q] = cprev[(size_t)r*HH + j0 + jj];
        }

        float acc[4][2][4];
#pragma unroll
        for (int a=0;a<4;++a)
#pragma unroll
        for (int b=0;b<2;++b)
#pragma unroll
        for (int c2=0;c2<4;++c2) acc[a][b][c2] = 0.f;

        // ---- prologue: issue chunks 0 and 1 ----
#pragma unroll
        for (int pc = 0; pc < 2; ++pc){
            uint32_t dsta = Hba + (uint32_t)(pc * 2304 * 4);
#pragma unroll
            for (int i = 0; i < 8; ++i){
                int row = l_row + (i << 2);
                cp_async16(dsta + (row*36 + l_seg)*4,
                           htf + (size_t)row*HH + kb0 + (pc << 5) + l_seg);
            }
            cp_commit();
        }

        // ---- main loop: 2-deep pipeline over 8 chunks ----
#pragma unroll
        for (int c = 0; c < 8; ++c){
            if (c < 7) cp_wait<1>(); else cp_wait<0>();
            asm volatile("bar.sync %0, 64;" :: "r"(barid));
            if (c < 6){
                const int nb = (c + 2) % 3;
                uint32_t dsta = Hba + (uint32_t)(nb * 2304 * 4);
#pragma unroll
                for (int i = 0; i < 8; ++i){
                    int row = l_row + (i << 2);
                    cp_async16(dsta + (row*36 + l_seg)*4,
                               htf + (size_t)row*HH + kb0 + ((c+2) << 5) + l_seg);
                }
                cp_commit();
            }
            const float* Hbc = Hb + (c % 3) * 2304;
#pragma unroll
            for (int ks = 0; ks < 4; ++ks){
                const int kb = ks << 3;
                const int s = (c << 2) + ks;
#pragma unroll
                for (int mf = 0; mf < 4; ++mf){
                    const int r = (mf << 4) + g;
                    unsigned af[4];
                    af[0] = __float_as_uint(Hbc[r*36     + kb + qi]);
                    af[1] = __float_as_uint(Hbc[(r+8)*36 + kb + qi]);
                    af[2] = __float_as_uint(Hbc[r*36     + kb + qi + 4]);
                    af[3] = __float_as_uint(Hbc[(r+8)*36 + kb + qi + 4]);
                    mma_tf32(acc[mf][0], af, breg[s][0]);
                    mma_tf32(acc[mf][1], af, breg[s][1]);
                }
            }
        }

        // ---- stage Xg + split-K partials ----
#pragma unroll
        for (int q = 0; q < 2; ++q){
            int fi = tid + (q << 8);
            int row = fi >> 3, kv = (fi & 7) << 2;
            *(float4*)(Xs + row*36 + kv) = xr[q];
        }
        float* Pw = Ps + slab * (64*34);
#pragma unroll
        for (int mf = 0; mf < 4; ++mf){
            int r = (mf << 4) + g;
#pragma unroll
            for (int nf = 0; nf < 2; ++nf){
                int col = (ch << 4) + (nf << 3) + (qi << 1);
                *(float2*)(Pw + r*34 + col)     = make_float2(acc[mf][nf][0], acc[mf][nf][1]);
                *(float2*)(Pw + (r+8)*34 + col) = make_float2(acc[mf][nf][2], acc[mf][nf][3]);
            }
        }
        __syncthreads();

        // ---- combine: reduce 4 slabs + Xg, activations, write h/c ----
#pragma unroll
        for (int q = 0; q < 2; ++q){
            int it = tid + (q << 8);
            int r = it >> 3, jj = it & 7;
            int cb = jj << 2;
            int pr = r*34 + cb;
            float gf = Xs[r*36 + cb    ] + Ps[pr    ] + Ps[64*34 + pr    ] + Ps[2*64*34 + pr    ] + Ps[3*64*34 + pr    ];
            float gi = Xs[r*36 + cb + 1] + Ps[pr + 1] + Ps[64*34 + pr + 1] + Ps[2*64*34 + pr + 1] + Ps[3*64*34 + pr + 1];
            float gc = Xs[r*36 + cb + 2] + Ps[pr + 2] + Ps[64*34 + pr + 2] + Ps[2*64*34 + pr + 2] + Ps[3*64*34 + pr + 2];
            float go = Xs[r*36 + cb + 3] + Ps[pr + 3] + Ps[64*34 + pr + 3] + Ps[2*64*34 + pr + 3] + Ps[3*64*34 + pr + 3];
            float f = 1.f/(1.f + expf(-gf));
            float i = 1.f/(1.f + expf(-gi));
            float cand = tanhf(gc);
            float o = 1.f/(1.f + expf(-go));
            int jg = j0 + jj;
            float cn = f*cpf[q] + i*cand;
            float hn = o*tanhf(cn);
            cout[(size_t)r*HH + jg] = cn;
            hout[(size_t)r*HH + jg] = hn;
            htf_n[(size_t)r*HH + jg] = __uint_as_float(f2tf(hn));
        }

        grid_bar();
    }
}

// ---------------------------------------------------------------------------
// GEMM C: Y[m, v] = sum_k Htfa[slot1+m][k] * Wotf[k, v] + bout[v]
// Block tile 128x256, warp tile 64x64 (8 warps = 2x4). A base computed in
// device code (host-side __device__ symbol arithmetic reads the host shadow
// via ATS on GB300 -> silent zeros; R11 bug).
// ---------------------------------------------------------------------------
#define GO_SMEM ((2*128*36 + 2*32*264) * 4)   // 104448 bytes

__global__ __launch_bounds__(256, 1) void gemm_out2(const float* __restrict__ bout,
                                                    float* __restrict__ Y){
    extern __shared__ float smx[];
    float* As0 = smx;
    float* As1 = As0 + 128*36;
    float* Bs0 = As1 + 128*36;
    float* Bs1 = Bs0 + 32*264;
    const uint32_t As0a = (uint32_t)__cvta_generic_to_shared(As0);
    const uint32_t As1a = (uint32_t)__cvta_generic_to_shared(As1);
    const uint32_t Bs0a = (uint32_t)__cvta_generic_to_shared(Bs0);
    const uint32_t Bs1a = (uint32_t)__cvta_generic_to_shared(Bs1);

    const float* Atf = g_Htfa + (size_t)BB * HH;   // slot 1 = h_0

    const int m0 = blockIdx.y << 7;
    const int n0 = blockIdx.x << 8;
    const int tid = threadIdx.x;
    const int w = tid >> 5, lane = tid & 31;
    const int g = lane >> 2, qi = lane & 3;
    const int wm = (w & 1) << 6;
    const int wn = (w >> 1) << 6;

    float acc[4][8][4];
#pragma unroll
    for (int a=0;a<4;++a)
#pragma unroll
    for (int b=0;b<8;++b)
#pragma unroll
    for (int c2=0;c2<4;++c2) acc[a][b][c2] = 0.f;

    int a_row[4], a_kv[4];
#pragma unroll
    for (int q=0;q<4;++q){
        int fi = tid + (q<<8);
        a_row[q] = fi >> 3; a_kv[q] = (fi & 7) << 2;
    }
    int b_row[8], b_cv[8];
#pragma unroll
    for (int q=0;q<8;++q){
        int fi = tid + (q<<8);
        b_row[q] = fi >> 6; b_cv[q] = (fi & 63) << 2;
    }

#pragma unroll
    for (int q=0;q<4;++q)
        cp_async16(As0a + (a_row[q]*36 + a_kv[q])*4,
                   Atf + (size_t)(m0 + a_row[q])*HH + a_kv[q]);
#pragma unroll
    for (int q=0;q<8;++q)
        cp_async16(Bs0a + (b_row[q]*264 + b_cv[q])*4,
                   g_Wotf + (size_t)b_row[q]*VP + n0 + b_cv[q]);
    cp_commit();

    for (int kt = 0; kt < 32; ++kt){
        if (kt < 31){
            const int ko = (kt + 1) << 5;
            uint32_t Ad = (kt & 1) ? As0a : As1a;
            uint32_t Bd = (kt & 1) ? Bs0a : Bs1a;
#pragma unroll
            for (int q=0;q<4;++q)
                cp_async16(Ad + (a_row[q]*36 + a_kv[q])*4,
                           Atf + (size_t)(m0 + a_row[q])*HH + ko + a_kv[q]);
#pragma unroll
            for (int q=0;q<8;++q)
                cp_async16(Bd + (b_row[q]*264 + b_cv[q])*4,
                           g_Wotf + (size_t)(ko + b_row[q])*VP + n0 + b_cv[q]);
            cp_commit();
            cp_wait<1>();
        } else {
            cp_wait<0>();
        }
        __syncthreads();

        const float* Asc = (kt & 1) ? As1 : As0;
        const float* Bsc = (kt & 1) ? Bs1 : Bs0;
#pragma unroll
        for (int ks = 0; ks < 4; ++ks){
            const int kb = ks << 3;
            unsigned bfr[8][2];
#pragma unroll
            for (int nf = 0; nf < 8; ++nf){
                int cc = wn + (nf << 3) + g;
                bfr[nf][0] = __float_as_uint(Bsc[(kb + qi    )*264 + cc]);
                bfr[nf][1] = __float_as_uint(Bsc[(kb + qi + 4)*264 + cc]);
            }
#pragma unroll
            for (int mf = 0; mf < 4; ++mf){
                int r = wm + (mf << 4) + g;
                unsigned af[4];
                af[0] = __float_as_uint(Asc[r*36       + kb + qi]);
                af[1] = __float_as_uint(Asc[(r+8)*36   + kb + qi]);
                af[2] = __float_as_uint(Asc[r*36       + kb + qi + 4]);
                af[3] = __float_as_uint(Asc[(r+8)*36   + kb + qi + 4]);
#pragma unroll
                for (int nf = 0; nf < 8; ++nf)
                    mma_tf32(acc[mf][nf], af, bfr[nf]);
            }
        }
        __syncthreads();
    }

#pragma unroll
    for (int mf = 0; mf < 4; ++mf){
        int r0 = m0 + wm + (mf << 4) + g;
#pragma unroll
        for (int nf = 0; nf < 8; ++nf){
            int col = n0 + wn + (nf << 3) + (qi << 1);
            if (col < VV){
                float b0 = bout[col], b1 = bout[col+1];
                *(float2*)(Y + (size_t)r0*VV + col) =
                    make_float2(acc[mf][nf][0] + b0, acc[mf][nf][1] + b1);
                *(float2*)(Y + (size_t)(r0+8)*VV + col) =
                    make_float2(acc[mf][nf][2] + b0, acc[mf][nf][3] + b1);
            }
        }
    }
}

// ---------------------------------------------------------------------------
// Launch: pack + round -> x-projection -> persistent recurrence -> output GEMM
// d_out layout (float32): all_h [T,B,H] | all_c [T,B,H] | all_y [T,B,V]
// ---------------------------------------------------------------------------
extern "C" void kernel_launch(void* const* d_in, const int* in_sizes, int n_in,
                              void* d_out, int out_size){
    (void)in_sizes; (void)n_in; (void)out_size;
    const int*   x      = (const int*)  d_in[0];
    const float* h_in   = (const float*)d_in[1];
    const float* c_in   = (const float*)d_in[2];
    const float* emb    = (const float*)d_in[3];
    const float* Wf_w   = (const float*)d_in[4];
    const float* Wf_b   = (const float*)d_in[5];
    const float* Wi_w   = (const float*)d_in[6];
    const float* Wi_b   = (const float*)d_in[7];
    const float* Wc_w   = (const float*)d_in[8];
    const float* Wc_b   = (const float*)d_in[9];
    const float* Wo_w   = (const float*)d_in[10];
    const float* Wo_b   = (const float*)d_in[11];
    const float* Wout_w = (const float*)d_in[12];
    const float* Wout_b = (const float*)d_in[13];
    float* out = (float*)d_out;

    static int attr_done = 0;
    if (!attr_done){
        cudaFuncSetAttribute(lstm_steps, cudaFuncAttributeMaxDynamicSharedMemorySize,
                             SMEM_LSTM);
        cudaFuncSetAttribute(gemm_out2, cudaFuncAttributeMaxDynamicSharedMemorySize,
                             GO_SMEM);
        attr_done = 1;
    }

    pack_kernel<<<256, 256>>>(Wf_w, Wi_w, Wc_w, Wo_w, Wf_b, Wi_b, Wc_b, Wo_b);
    round_wout<<<512, 256>>>(Wout_w);

    gemm_xproj<<<dim3(NG/128, MALL/128), 256>>>(x, emb);

    lstm_steps<<<NBLK, 256, SMEM_LSTM>>>(h_in, c_in, out);

    gemm_out2<<<dim3(VP/256, MALL/128), 256, GO_SMEM>>>(Wout_b, out + YBASE);
}